// round 2
// baseline (speedup 1.0000x reference)
#include <cuda_runtime.h>
#include <cstdint>

// Haar 2x2 wavelet: in (16,32,512,512) f32 -> out (16,128,256,256) f32
// out[b][0*32+c] = pooled, [1*32+c] = diff_h, [2*32+c] = diff_v, [3*32+c] = diff_d
//
// Memory-bound: 512 MiB in + 512 MiB out. Each thread:
//   loads  4x float4 (8 cols x 2 rows of input)
//   stores 4x float4 (4 output pixels in each of the 4 channel groups)

#define B_  16
#define C_  32
#define H_  512
#define W_  512
#define HO_ 256
#define WO_ 256

__global__ __launch_bounds__(256) void haar_kernel(
    const float* __restrict__ x, float* __restrict__ out)
{
    // One thread = 4 output pixels (float4 wide) at (bc, h, w4*4..w4*4+3)
    // total threads = B*C*HO*(WO/4) = 16*32*256*64 = 8,388,608
    const uint32_t t = blockIdx.x * blockDim.x + threadIdx.x;

    const uint32_t w4  = t & 63u;          // WO/4 = 64
    uint32_t tmp       = t >> 6;
    const uint32_t h   = tmp & 255u;       // HO = 256
    const uint32_t bc  = tmp >> 8;         // 0..511 (b*C + c)

    // ---- input loads: rows 2h and 2h+1, cols 8*w4 .. 8*w4+7 ----
    const float* row0 = x + ((size_t)bc * (H_ * W_)) + (size_t)(2u * h) * W_ + w4 * 8u;
    const float* row1 = row0 + W_;

    const float4 t0 = *reinterpret_cast<const float4*>(row0);
    const float4 t1 = *reinterpret_cast<const float4*>(row0 + 4);
    const float4 b0 = *reinterpret_cast<const float4*>(row1);
    const float4 b1 = *reinterpret_cast<const float4*>(row1 + 4);

    // pairs: (a,b) from top row, (c,d) from bottom row
    const float a0 = t0.x, bb0 = t0.y, c0 = b0.x, d0 = b0.y;
    const float a1 = t0.z, bb1 = t0.w, c1 = b0.z, d1 = b0.w;
    const float a2 = t1.x, bb2 = t1.y, c2 = b1.x, d2 = b1.y;
    const float a3 = t1.z, bb3 = t1.w, c3 = b1.z, d3 = b1.w;

    float4 pooled, dh, dv, dd;

    pooled.x = (a0 + bb0 + c0 + d0) * 0.25f;
    pooled.y = (a1 + bb1 + c1 + d1) * 0.25f;
    pooled.z = (a2 + bb2 + c2 + d2) * 0.25f;
    pooled.w = (a3 + bb3 + c3 + d3) * 0.25f;

    dh.x = (a0 + bb0 - c0 - d0) * 0.5f;
    dh.y = (a1 + bb1 - c1 - d1) * 0.5f;
    dh.z = (a2 + bb2 - c2 - d2) * 0.5f;
    dh.w = (a3 + bb3 - c3 - d3) * 0.5f;

    dv.x = (a0 + c0 - bb0 - d0) * 0.5f;
    dv.y = (a1 + c1 - bb1 - d1) * 0.5f;
    dv.z = (a2 + c2 - bb2 - d2) * 0.5f;
    dv.w = (a3 + c3 - bb3 - d3) * 0.5f;

    dd.x = a0 - bb0 - c0 + d0;
    dd.y = a1 - bb1 - c1 + d1;
    dd.z = a2 - bb2 - c2 + d2;
    dd.w = a3 - bb3 - c3 + d3;

    // ---- output stores ----
    const uint32_t b_idx = bc >> 5;        // /32
    const uint32_t ch    = bc & 31u;       // %32
    // out[b][g*32+ch][h][w]; plane = HO*WO = 65536
    const size_t plane = (size_t)HO_ * WO_;
    float* obase = out + ((size_t)b_idx * (4 * C_) + ch) * plane
                       + (size_t)h * WO_ + w4 * 4u;

    *reinterpret_cast<float4*>(obase)                   = pooled;  // group 0
    *reinterpret_cast<float4*>(obase + 1 * C_ * plane)  = dh;      // group 1
    *reinterpret_cast<float4*>(obase + 2 * C_ * plane)  = dv;      // group 2
    *reinterpret_cast<float4*>(obase + 3 * C_ * plane)  = dd;      // group 3
}

extern "C" void kernel_launch(void* const* d_in, const int* in_sizes, int n_in,
                              void* d_out, int out_size)
{
    const float* x = (const float*)d_in[0];
    float* out = (float*)d_out;

    const uint32_t total_threads = B_ * C_ * HO_ * (WO_ / 4);  // 8,388,608
    const uint32_t block = 256;
    const uint32_t grid = total_threads / block;               // 32768

    haar_kernel<<<grid, block>>>(x, out);
}